// round 13
// baseline (speedup 1.0000x reference)
#include <cuda_runtime.h>
#include <cuda_fp16.h>
#include <cstdint>

#define BDIM   8192
#define DDIM   2048
#define NUNITS 2048
#define WB     56              // bit words (k < 1792)
#define NSTAGE 8               // 7 bit-words + 32 fp16-k per stage

#define ABITS_TILE (WB * 128)  // 7168 u32
#define BBITS_TILE (WB * 64)   // 3584 u32
#define AF_TILE (128 * 128)    // [r][h] u32(half2) per 128-row tile
#define BF_TILE (128 * 64)     // [h][c] u32(half2) per 64-col tile
#define FBUF_U32 3072          // per buffer: A 2048 + B 1024
#define GEMM_SMEM ((ABITS_TILE + BBITS_TILE + 2 * FBUF_U32 + 4) * 4)   // 67600 B

__device__ __align__(128) uint32_t g_Abits[(size_t)(BDIM / 128) * ABITS_TILE];
__device__ __align__(128) uint32_t g_Bbits[(size_t)(NUNITS / 64) * BBITS_TILE];
__device__ __align__(128) uint32_t g_Af[(size_t)(BDIM / 128) * AF_TILE];
__device__ __align__(128) uint32_t g_Bf[(size_t)(NUNITS / 64) * BF_TILE];

// ============================ PTX helpers ============================

__device__ __forceinline__ uint32_t smem_u32(const void* p) {
    uint32_t a;
    asm("{ .reg .u64 t; cvta.to.shared.u64 t, %1; cvt.u32.u64 %0, t; }" : "=r"(a) : "l"(p));
    return a;
}
__device__ __forceinline__ void cp_async16(uint32_t dst, const void* src) {
    asm volatile("cp.async.cg.shared.global [%0], [%1], 16;" :: "r"(dst), "l"(src) : "memory");
}
#define CP_COMMIT() asm volatile("cp.async.commit_group;" ::: "memory")
#define CP_WAIT(n)  asm volatile("cp.async.wait_group %0;" :: "n"(n) : "memory")

__device__ __forceinline__ __half2 u2h(uint32_t v) {
    __half2 h; *reinterpret_cast<uint32_t*>(&h) = v; return h;
}

// ============================ Pack kernels ============================

// warp w: row m = w>>2, segs (w&3)*4 .. +3 (128 k each). segs<14 -> bits; 14,15 -> half2
__global__ void pack_a(const float* __restrict__ in,
                       uint32_t* __restrict__ bits, uint32_t* __restrict__ af) {
    int lane = threadIdx.x & 31;
    int warp = (blockIdx.x * blockDim.x + threadIdx.x) >> 5;
    int m   = warp >> 2;
    int sg0 = (warp & 3) * 4;

    float4 v[4];
#pragma unroll
    for (int s = 0; s < 4; s++)
        v[s] = *(const float4*)&in[(size_t)m * DDIM + (sg0 + s) * 128 + lane * 4];

    int mt = m >> 7, mr = m & 127;
    uint32_t* bbase = bits + (size_t)mt * ABITS_TILE + mr;
    uint32_t* fbase = af + (size_t)mt * AF_TILE + mr * 128;   // [r][h]
#pragma unroll
    for (int s = 0; s < 4; s++) {
        int seg = sg0 + s;
        if (seg < 14) {
            uint32_t w0 = __ballot_sync(0xFFFFFFFFu, v[s].x < 0.0f);
            uint32_t w1 = __ballot_sync(0xFFFFFFFFu, v[s].y < 0.0f);
            uint32_t w2 = __ballot_sync(0xFFFFFFFFu, v[s].z < 0.0f);
            uint32_t w3 = __ballot_sync(0xFFFFFFFFu, v[s].w < 0.0f);
            if (lane == 0) {
                bbase[(seg * 4 + 0) * 128] = w0;
                bbase[(seg * 4 + 1) * 128] = w1;
                bbase[(seg * 4 + 2) * 128] = w2;
                bbase[(seg * 4 + 3) * 128] = w3;
            }
        } else {
            int h = (seg - 14) * 64 + 2 * lane;
            uint32_t lo = (v[s].x < 0.f ? 0xBC00u : 0x3C00u) |
                          ((v[s].y < 0.f ? 0xBC00u : 0x3C00u) << 16);
            uint32_t hi = (v[s].z < 0.f ? 0xBC00u : 0x3C00u) |
                          ((v[s].w < 0.f ? 0xBC00u : 0x3C00u) << 16);
            *(uint2*)&fbase[h] = make_uint2(lo, hi);
        }
    }
}

// block: 128 k x 32 n. blockIdx.y<14 -> bits (word j=4*by+q); by 14,15 -> half2 [h][c]
__global__ void pack_b(const float* __restrict__ kern,
                       uint32_t* __restrict__ bits, uint32_t* __restrict__ bf) {
    __shared__ uint8_t tile[128 * 33];
    int n0 = blockIdx.x * 32;
    int kb = blockIdx.y * 128;
    int tx = threadIdx.x, ty = threadIdx.y;   // (32, 8)
#pragma unroll
    for (int s = 0; s < 16; s++) {
        int k = ty + s * 8;
        float v = kern[(size_t)(kb + k) * NUNITS + n0 + tx];
        tile[k * 33 + tx] = (v < 0.0f) ? 1 : 0;
    }
    __syncthreads();

    if (blockIdx.y < 14) {
        int lane = tx;
#pragma unroll
        for (int nl = 0; nl < 4; nl++) {
            int n = n0 + ty * 4 + nl;
            uint32_t* dst = bits + (size_t)(n >> 6) * BBITS_TILE + (n & 63);
#pragma unroll
            for (int q = 0; q < 4; q++) {
                uint8_t val = tile[(4 * lane + q) * 33 + (ty * 4 + nl)];
                uint32_t word = __ballot_sync(0xFFFFFFFFu, val != 0);
                if (lane == 0)
                    dst[(blockIdx.y * 4 + q) * 64] = word;
            }
        }
    } else {
        int n = n0 + tx;
        uint32_t* dst = bf + (size_t)(n >> 6) * BF_TILE + (n & 63);
#pragma unroll
        for (int i = 0; i < 8; i++) {
            int hl = ty * 8 + i;
            uint32_t lo = tile[(2 * hl) * 33 + tx]     ? 0xBC00u : 0x3C00u;
            uint32_t hi = tile[(2 * hl + 1) * 33 + tx] ? 0xBC00u : 0x3C00u;
            dst[((blockIdx.y - 14) * 64 + hl) * 64] = lo | (hi << 16);
        }
    }
}

// ============================ dual-pipe GEMM ============================
// out[m][n] = (1792 - 2*P) + H + bias ; P = popc over 56 words (alu pipe),
// H = fp16 dot over 256 k via HFMA2 (fma pipe), interleaved per stage.

__global__ void __launch_bounds__(256, 2) popc_gemm(
    const uint32_t* __restrict__ Ab, const uint32_t* __restrict__ Bb,
    const uint32_t* __restrict__ Af, const uint32_t* __restrict__ Bf,
    const float* __restrict__ bias, float* __restrict__ out)
{
    extern __shared__ uint32_t sm[];
    uint32_t* bitsA = sm;
    uint32_t* bitsB = sm + ABITS_TILE;
    uint32_t* fbuf  = sm + ABITS_TILE + BBITS_TILE;
    int* ksm = (int*)(sm + ABITS_TILE + BBITS_TILE + 2 * FBUF_U32);

    const int tid = threadIdx.x;
    const int nblk = blockIdx.x, mblk = blockIdx.y;
    if (tid == 0) { ksm[0] = 1; ksm[1] = 2; }

    // one-shot bits copy
    {
        const uint4* gA = (const uint4*)(Ab + (size_t)mblk * ABITS_TILE);
        uint4* sA = (uint4*)bitsA;
#pragma unroll
        for (int i = 0; i < 7; i++) sA[tid + i * 256] = gA[tid + i * 256];
        const uint4* gB = (const uint4*)(Bb + (size_t)nblk * BBITS_TILE);
        uint4* sB = (uint4*)bitsB;
#pragma unroll
        for (int i = 0; i < 4; i++) {
            int idx = tid + i * 256;
            if (idx < 896) sB[idx] = gB[idx];
        }
    }

    const char* gAf = (const char*)(Af + (size_t)mblk * AF_TILE);
    const char* gBf = (const char*)(Bf + (size_t)nblk * BF_TILE);
    const uint32_t fb = smem_u32(fbuf);
    const int crow = tid >> 1, chalf = tid & 1;

    // prologue: fp16 stage 0 -> buf 0
    cp_async16(fb + (crow * 16 + chalf * 8) * 4,       gAf + (crow * 128 + chalf * 8) * 4);
    cp_async16(fb + (crow * 16 + chalf * 8 + 4) * 4,   gAf + (crow * 128 + chalf * 8 + 4) * 4);
    cp_async16(fb + (2048 + tid * 4) * 4,              gBf + (tid * 4) * 4);
    CP_COMMIT();
    __syncthreads();

    const int k1 = ksm[0];                    // == 1, opaque -> IMAD on fma pipe
    const int k2 = ksm[1];                    // == 2
    const int tx = tid & 15, ty = tid >> 4;

    int acc[8][4];
    __half2 hacc[8][4];
#pragma unroll
    for (int i = 0; i < 8; i++)
#pragma unroll
        for (int k = 0; k < 4; k++) { acc[i][k] = 0; hacc[i][k] = u2h(0u); }

#define FP16_UNIT(u) do {                                                        \
        uint32_t ah[8][2];                                                       \
        _Pragma("unroll")                                                        \
        for (int mi = 0; mi < 8; mi++)                                           \
            *(uint2*)&ah[mi][0] = *(const uint2*)&fA[(ty * 8 + mi) * 16 + 2 * (u)]; \
        uint4 bq0 = *(const uint4*)&fB[(2 * (u)) * 64 + tx * 4];                 \
        uint4 bq1 = *(const uint4*)&fB[(2 * (u) + 1) * 64 + tx * 4];             \
        uint32_t bh[4][2] = {{bq0.x, bq1.x}, {bq0.y, bq1.y},                     \
                             {bq0.z, bq1.z}, {bq0.w, bq1.w}};                    \
        _Pragma("unroll")                                                        \
        for (int mi = 0; mi < 8; mi++)                                           \
            _Pragma("unroll")                                                    \
            for (int ni = 0; ni < 4; ni++) {                                     \
                hacc[mi][ni] = __hfma2(u2h(ah[mi][0]), u2h(bh[ni][0]), hacc[mi][ni]); \
                hacc[mi][ni] = __hfma2(u2h(ah[mi][1]), u2h(bh[ni][1]), hacc[mi][ni]); \
            }                                                                    \
    } while (0)

#define TRIPLE(w) do {                                                           \
        uint32_t a0[8], a1[8], a2[8], b0[4], b1[4], b2[4];                       \
        const uint32_t* Ap = &bitsA[(w) * 128 + ty * 8];                         \
        const uint32_t* Bp = &bitsB[(w) * 64 + tx * 4];                          \
        *(uint4*)&a0[0] = *(const uint4*)&Ap[0];   *(uint4*)&a0[4] = *(const uint4*)&Ap[4];   \
        *(uint4*)&a1[0] = *(const uint4*)&Ap[128]; *(uint4*)&a1[4] = *(const uint4*)&Ap[132]; \
        *(uint4*)&a2[0] = *(const uint4*)&Ap[256]; *(uint4*)&a2[4] = *(const uint4*)&Ap[260]; \
        *(uint4*)&b0[0] = *(const uint4*)&Bp[0];                                 \
        *(uint4*)&b1[0] = *(const uint4*)&Bp[64];                                \
        *(uint4*)&b2[0] = *(const uint4*)&Bp[128];                               \
        _Pragma("unroll")                                                        \
        for (int mi = 0; mi < 8; mi++)                                           \
            _Pragma("unroll")                                                    \
            for (int ni = 0; ni < 4; ni++) {                                     \
                uint32_t x0 = a0[mi] ^ b0[ni];                                   \
                uint32_t x1 = a1[mi] ^ b1[ni];                                   \
                uint32_t x2 = a2[mi] ^ b2[ni];                                   \
                uint32_t s_ = x0 ^ x1 ^ x2;                                      \
                uint32_t c_ = (x0 & x1) | (x2 & (x0 | x1));                      \
                int a = acc[mi][ni];                                             \
                a = __popc(s_) * k1 + a;                                         \
                a = __popc(c_) * k2 + a;                                         \
                acc[mi][ni] = a;                                                 \
            }                                                                    \
    } while (0)

#define RAWW(w) do {                                                             \
        uint32_t ar[8], br[4];                                                   \
        const uint32_t* Ap = &bitsA[(w) * 128 + ty * 8];                         \
        const uint32_t* Bp = &bitsB[(w) * 64 + tx * 4];                          \
        *(uint4*)&ar[0] = *(const uint4*)&Ap[0]; *(uint4*)&ar[4] = *(const uint4*)&Ap[4]; \
        *(uint4*)&br[0] = *(const uint4*)&Bp[0];                                 \
        _Pragma("unroll")                                                        \
        for (int mi = 0; mi < 8; mi++)                                           \
            _Pragma("unroll")                                                    \
            for (int ni = 0; ni < 4; ni++)                                       \
                acc[mi][ni] = __popc(ar[mi] ^ br[ni]) * k1 + acc[mi][ni];        \
    } while (0)

#pragma unroll 1
    for (int s = 0; s < NSTAGE; s++) {
        CP_WAIT(0);
        __syncthreads();
        if (s < NSTAGE - 1) {
            uint32_t nb = fb + ((s + 1) & 1) * FBUF_U32 * 4;
            cp_async16(nb + (crow * 16 + chalf * 8) * 4,
                       gAf + (crow * 128 + (s + 1) * 16 + chalf * 8) * 4);
            cp_async16(nb + (crow * 16 + chalf * 8 + 4) * 4,
                       gAf + (crow * 128 + (s + 1) * 16 + chalf * 8 + 4) * 4);
            cp_async16(nb + (2048 + tid * 4) * 4,
                       gBf + ((s + 1) * 1024 + tid * 4) * 4);
            CP_COMMIT();
        }
        const uint32_t* fA = fbuf + (s & 1) * FBUF_U32;
        const uint32_t* fB = fA + 2048;
        const int w0 = s * 7;

        FP16_UNIT(0); FP16_UNIT(1);
        TRIPLE(w0);
        FP16_UNIT(2); FP16_UNIT(3);
        TRIPLE(w0 + 3);
        FP16_UNIT(4); FP16_UNIT(5);
        RAWW(w0 + 6);
        FP16_UNIT(6); FP16_UNIT(7);
    }

    // epilogue: out = (1792 - 2*P) + H + bias
    const int n0 = nblk * 64 + tx * 4;
    float bl[4];
    *(float4*)&bl[0] = *(const float4*)&bias[n0];
#pragma unroll
    for (int i = 0; i < 4; i++) bl[i] += 1792.0f;

#pragma unroll
    for (int mi = 0; mi < 8; mi++) {
        size_t row = (size_t)(mblk * 128 + ty * 8 + mi) * NUNITS + n0;
        float4 v0;
        float h0 = __low2float(hacc[mi][0]) + __high2float(hacc[mi][0]);
        float h1 = __low2float(hacc[mi][1]) + __high2float(hacc[mi][1]);
        float h2v = __low2float(hacc[mi][2]) + __high2float(hacc[mi][2]);
        float h3 = __low2float(hacc[mi][3]) + __high2float(hacc[mi][3]);
        v0.x = fmaf(-2.0f, (float)acc[mi][0], bl[0] + h0);
        v0.y = fmaf(-2.0f, (float)acc[mi][1], bl[1] + h1);
        v0.z = fmaf(-2.0f, (float)acc[mi][2], bl[2] + h2v);
        v0.w = fmaf(-2.0f, (float)acc[mi][3], bl[3] + h3);
        *(float4*)&out[row] = v0;
    }
}

// ============================ Host ============================

extern "C" void kernel_launch(void* const* d_in, const int* in_sizes, int n_in,
                              void* d_out, int out_size) {
    const float* inputs = (const float*)d_in[0];
    const float* kern   = (const float*)d_in[1];
    const float* bias   = (const float*)d_in[2];
    float* out = (float*)d_out;

    void *pAb = nullptr, *pBb = nullptr, *pAf = nullptr, *pBf = nullptr;
    cudaGetSymbolAddress(&pAb, g_Abits);
    cudaGetSymbolAddress(&pBb, g_Bbits);
    cudaGetSymbolAddress(&pAf, g_Af);
    cudaGetSymbolAddress(&pBf, g_Bf);

    // 1) pack A (bits + half2), warp per (row, 4 segs)
    pack_a<<<(BDIM * 4) / 8, 256>>>(inputs, (uint32_t*)pAb, (uint32_t*)pAf);

    // 2) pack B (bits + half2), 128k x 32n tile per block
    {
        dim3 tb(32, 8), tg(NUNITS / 32, DDIM / 128);   // (64, 16)
        pack_b<<<tg, tb>>>(kern, (uint32_t*)pBb, (uint32_t*)pBf);
    }

    // 3) dual-pipe GEMM: 128x64 tiles, 2 CTAs/SM
    cudaFuncSetAttribute(popc_gemm, cudaFuncAttributeMaxDynamicSharedMemorySize, GEMM_SMEM);
    dim3 grid(NUNITS / 64, BDIM / 128);        // (32, 64)
    popc_gemm<<<grid, 256, GEMM_SMEM>>>((const uint32_t*)pAb, (const uint32_t*)pBb,
                                        (const uint32_t*)pAf, (const uint32_t*)pBf,
                                        bias, out);
}

// round 14
// speedup vs baseline: 1.4986x; 1.4986x over previous
#include <cuda_runtime.h>
#include <cstdint>

// Problem shape
#define BDIM   8192
#define DDIM   2048
#define NUNITS 2048
#define KW     64          // 2048 bits = 64 u32 words per row

// A bits: [128-row tile][j][rowInTile] ; B bits: [64-col tile][j][colInTile]
// Bit order inside words is permuted identically for A and B (XOR/POPC invariant).
__device__ __align__(128) uint32_t g_Abits[(size_t)(BDIM / 128) * KW * 128];   // 2 MB
__device__ __align__(128) uint32_t g_Bbits[(size_t)(NUNITS / 64) * KW * 64];   // 512 KB

// ============================ Merged pack kernel ============================
// Blocks [0, 4096): pack A (warp per (row, 4 segs), 8 warps/block).
// Blocks [4096, 5120): pack B (128k x 32n tile per block).
// Single launch -> A-bound and B-bound DRAM traffic overlap.

#define PACKA_BLOCKS 4096

__global__ void __launch_bounds__(256) pack_all(
    const float* __restrict__ in, const float* __restrict__ kern,
    uint32_t* __restrict__ abits, uint32_t* __restrict__ bbits)
{
    __shared__ uint8_t tile[128 * 33];        // only used by B role (4.2 KB)
    const int tid = threadIdx.x;

    if (blockIdx.x < PACKA_BLOCKS) {
        // ---- A role ----
        int lane = tid & 31;
        int warp = (blockIdx.x * 256 + tid) >> 5;
        int m   = warp >> 2;
        int sg0 = (warp & 3) * 4;

        float4 v[4];
#pragma unroll
        for (int s = 0; s < 4; s++)
            v[s] = *(const float4*)&in[(size_t)m * DDIM + (sg0 + s) * 128 + lane * 4];

        uint32_t* base = abits + (size_t)(m >> 7) * (KW * 128) + (m & 127);
#pragma unroll
        for (int s = 0; s < 4; s++) {
            int j0 = (sg0 + s) * 4;
            uint32_t w0 = __ballot_sync(0xFFFFFFFFu, v[s].x < 0.0f);
            uint32_t w1 = __ballot_sync(0xFFFFFFFFu, v[s].y < 0.0f);
            uint32_t w2 = __ballot_sync(0xFFFFFFFFu, v[s].z < 0.0f);
            uint32_t w3 = __ballot_sync(0xFFFFFFFFu, v[s].w < 0.0f);
            if (lane == 0) {
                base[(j0 + 0) * 128] = w0;
                base[(j0 + 1) * 128] = w1;
                base[(j0 + 2) * 128] = w2;
                base[(j0 + 3) * 128] = w3;
            }
        }
    } else {
        // ---- B role: word j = 4*by + q, bit l = sign(kern[128*by + 4l + q][n]) ----
        int bid = blockIdx.x - PACKA_BLOCKS;
        int n0 = (bid & 63) * 32;             // 64 n-tiles
        int by = bid >> 6;                    // 16 k-tiles
        int kb = by * 128;
        int tx = tid & 31, ty = tid >> 5;     // (32, 8)
#pragma unroll
        for (int s = 0; s < 16; s++) {
            int k = ty + s * 8;
            float v = kern[(size_t)(kb + k) * NUNITS + n0 + tx];
            tile[k * 33 + tx] = (v < 0.0f) ? 1 : 0;
        }
        __syncthreads();

        int lane = tx;                        // warp = ty
#pragma unroll
        for (int nl = 0; nl < 4; nl++) {
            int n = n0 + ty * 4 + nl;
            uint32_t* dst = bbits + (size_t)(n >> 6) * (KW * 64) + (n & 63);
#pragma unroll
            for (int q = 0; q < 4; q++) {
                uint8_t val = tile[(4 * lane + q) * 33 + (ty * 4 + nl)];
                uint32_t word = __ballot_sync(0xFFFFFFFFu, val != 0);
                if (lane == 0)
                    dst[(by * 4 + q) * 64] = word;
            }
        }
    }
}

// ============================ popcount GEMM (128x64 tiles) ============================
// out[m][n] = 2048 - 2 * sum_j popc(A[m][j] ^ B[n][j]) + bias[n]
// 2048 CTAs -> 6.92 tiles per resident slot -> 1.2% wave tail.

__global__ void __launch_bounds__(256, 2) popc_gemm(
    const uint32_t* __restrict__ Ab, const uint32_t* __restrict__ Bb,
    const float* __restrict__ bias, float* __restrict__ out)
{
    extern __shared__ uint32_t smem[];        // A 8192 words, B 4096 words, k1/k2
    uint32_t* Asm = smem;
    uint32_t* Bsm = smem + KW * 128;
    int* ksm = (int*)(smem + KW * 128 + KW * 64);

    const int tid = threadIdx.x;
    const int nblk = blockIdx.x, mblk = blockIdx.y;

    if (tid == 0) { ksm[0] = 1; ksm[1] = 2; }

    {
        const uint4* gA = (const uint4*)(Ab + (size_t)mblk * (KW * 128));
        uint4* sA = (uint4*)Asm;
#pragma unroll
        for (int i = 0; i < 8; i++)
            sA[tid + i * 256] = gA[tid + i * 256];
        const uint4* gB = (const uint4*)(Bb + (size_t)nblk * (KW * 64));
        uint4* sB = (uint4*)Bsm;
#pragma unroll
        for (int i = 0; i < 4; i++)
            sB[tid + i * 256] = gB[tid + i * 256];
    }
    __syncthreads();

    const int k1 = ksm[0];                    // == 1, opaque -> IMAD on fma pipe
    const int k2 = ksm[1];                    // == 2, opaque
    const int tx = tid & 15;                  // 16 n-subblocks x 4 cols
    const int ty = tid >> 4;                  // 16 m-subblocks x 8 rows

    int acc[8][4];
#pragma unroll
    for (int i = 0; i < 8; i++)
#pragma unroll
        for (int k = 0; k < 4; k++) acc[i][k] = 0;

    // 20 CSA triples (words 0..59)
#pragma unroll 2
    for (int jg = 0; jg < 20; jg++) {
        uint32_t a0[8], a1[8], a2[8], b0[4], b1[4], b2[4];
        const uint32_t* Ap = &Asm[(jg * 3) * 128 + ty * 8];
        const uint32_t* Bp = &Bsm[(jg * 3) * 64 + tx * 4];
        *(uint4*)&a0[0] = *(const uint4*)&Ap[0];   *(uint4*)&a0[4] = *(const uint4*)&Ap[4];
        *(uint4*)&a1[0] = *(const uint4*)&Ap[128]; *(uint4*)&a1[4] = *(const uint4*)&Ap[132];
        *(uint4*)&a2[0] = *(const uint4*)&Ap[256]; *(uint4*)&a2[4] = *(const uint4*)&Ap[260];
        *(uint4*)&b0[0] = *(const uint4*)&Bp[0];
        *(uint4*)&b1[0] = *(const uint4*)&Bp[64];
        *(uint4*)&b2[0] = *(const uint4*)&Bp[128];
#pragma unroll
        for (int mi = 0; mi < 8; mi++) {
#pragma unroll
            for (int ni = 0; ni < 4; ni++) {
                uint32_t x0 = a0[mi] ^ b0[ni];
                uint32_t x1 = a1[mi] ^ b1[ni];
                uint32_t x2 = a2[mi] ^ b2[ni];
                uint32_t s = x0 ^ x1 ^ x2;                      // LOP3 0x96
                uint32_t c = (x0 & x1) | (x2 & (x0 | x1));      // LOP3 0xE8
                int a = acc[mi][ni];
                a = __popc(s) * k1 + a;                         // IMAD (fma pipe)
                a = __popc(c) * k2 + a;                         // IMAD (fma pipe)
                acc[mi][ni] = a;
            }
        }
    }
    // raw tail: words 60..63
    {
        uint32_t a0[8], a1[8], a2[8], a3[8], b0[4], b1[4], b2[4], b3[4];
        const uint32_t* Ap = &Asm[60 * 128 + ty * 8];
        const uint32_t* Bp = &Bsm[60 * 64 + tx * 4];
        *(uint4*)&a0[0] = *(const uint4*)&Ap[0];   *(uint4*)&a0[4] = *(const uint4*)&Ap[4];
        *(uint4*)&a1[0] = *(const uint4*)&Ap[128]; *(uint4*)&a1[4] = *(const uint4*)&Ap[132];
        *(uint4*)&a2[0] = *(const uint4*)&Ap[256]; *(uint4*)&a2[4] = *(const uint4*)&Ap[260];
        *(uint4*)&a3[0] = *(const uint4*)&Ap[384]; *(uint4*)&a3[4] = *(const uint4*)&Ap[388];
        *(uint4*)&b0[0] = *(const uint4*)&Bp[0];
        *(uint4*)&b1[0] = *(const uint4*)&Bp[64];
        *(uint4*)&b2[0] = *(const uint4*)&Bp[128];
        *(uint4*)&b3[0] = *(const uint4*)&Bp[192];
#pragma unroll
        for (int mi = 0; mi < 8; mi++) {
#pragma unroll
            for (int ni = 0; ni < 4; ni++) {
                int a = acc[mi][ni];
                a = __popc(a0[mi] ^ b0[ni]) * k1 + a;
                a = __popc(a1[mi] ^ b1[ni]) * k1 + a;
                a = __popc(a2[mi] ^ b2[ni]) * k1 + a;
                a = __popc(a3[mi] ^ b3[ni]) * k1 + a;
                acc[mi][ni] = a;
            }
        }
    }

    // epilogue: val = 2048 - 2*acc + bias
    const int n0 = nblk * 64 + tx * 4;
    float bl[4];
    *(float4*)&bl[0] = *(const float4*)&bias[n0];
#pragma unroll
    for (int i = 0; i < 4; i++) bl[i] += 2048.0f;

#pragma unroll
    for (int mi = 0; mi < 8; mi++) {
        size_t row = (size_t)(mblk * 128 + ty * 8 + mi) * NUNITS + n0;
        float4 v0;
        v0.x = fmaf(-2.0f, (float)acc[mi][0], bl[0]);
        v0.y = fmaf(-2.0f, (float)acc[mi][1], bl[1]);
        v0.z = fmaf(-2.0f, (float)acc[mi][2], bl[2]);
        v0.w = fmaf(-2.0f, (float)acc[mi][3], bl[3]);
        *(float4*)&out[row] = v0;
    }
}

// ============================ Host ============================

#define GEMM_SMEM ((KW * 128 + KW * 64) * 4 + 16)   // 48 KB + k1/k2 -> 2 CTAs/SM

extern "C" void kernel_launch(void* const* d_in, const int* in_sizes, int n_in,
                              void* d_out, int out_size) {
    const float* inputs = (const float*)d_in[0];
    const float* kern   = (const float*)d_in[1];
    const float* bias   = (const float*)d_in[2];
    float* out = (float*)d_out;

    void *pA = nullptr, *pB = nullptr;
    cudaGetSymbolAddress(&pA, g_Abits);
    cudaGetSymbolAddress(&pB, g_Bbits);

    // 1) merged packs: A role (4096 blocks) + B role (1024 blocks), one launch
    pack_all<<<PACKA_BLOCKS + 1024, 256>>>(inputs, kern, (uint32_t*)pA, (uint32_t*)pB);

    // 2) CSA popcount GEMM, 128x64 tiles, 2 CTAs/SM
    cudaFuncSetAttribute(popc_gemm, cudaFuncAttributeMaxDynamicSharedMemorySize, GEMM_SMEM);
    dim3 grid(NUNITS / 64, BDIM / 128);        // (32, 64) = 2048 CTAs
    popc_gemm<<<grid, 256, GEMM_SMEM>>>((const uint32_t*)pA, (const uint32_t*)pB, bias, out);
}

// round 15
// speedup vs baseline: 1.5658x; 1.0449x over previous
#include <cuda_runtime.h>
#include <cstdint>

// Problem shape
#define BDIM   8192
#define DDIM   2048
#define NUNITS 2048
#define KW     64          // 2048 bits = 64 u32 words per row

// A bits: [128-row tile][j][rowInTile] ; B bits: [64-col tile][j][colInTile]
// Bit order inside words is permuted identically for A and B (XOR/POPC invariant).
__device__ __align__(128) uint32_t g_Abits[(size_t)(BDIM / 128) * KW * 128];   // 2 MB
__device__ __align__(128) uint32_t g_Bbits[(size_t)(NUNITS / 64) * KW * 64];   // 512 KB

// ============================ Merged pack kernel ============================
// Blocks [0, 4096): pack A. Blocks [4096, 5120): pack B. One launch.

#define PACKA_BLOCKS 4096

__global__ void __launch_bounds__(256) pack_all(
    const float* __restrict__ in, const float* __restrict__ kern,
    uint32_t* __restrict__ abits, uint32_t* __restrict__ bbits)
{
    __shared__ uint8_t tile[128 * 33];        // only used by B role
    const int tid = threadIdx.x;

    if (blockIdx.x < PACKA_BLOCKS) {
        // ---- A role: warp per (row, 4 segs of 128 k) ----
        int lane = tid & 31;
        int warp = (blockIdx.x * 256 + tid) >> 5;
        int m   = warp >> 2;
        int sg0 = (warp & 3) * 4;

        float4 v[4];
#pragma unroll
        for (int s = 0; s < 4; s++)
            v[s] = *(const float4*)&in[(size_t)m * DDIM + (sg0 + s) * 128 + lane * 4];

        uint32_t* base = abits + (size_t)(m >> 7) * (KW * 128) + (m & 127);
#pragma unroll
        for (int s = 0; s < 4; s++) {
            int j0 = (sg0 + s) * 4;
            uint32_t w0 = __ballot_sync(0xFFFFFFFFu, v[s].x < 0.0f);
            uint32_t w1 = __ballot_sync(0xFFFFFFFFu, v[s].y < 0.0f);
            uint32_t w2 = __ballot_sync(0xFFFFFFFFu, v[s].z < 0.0f);
            uint32_t w3 = __ballot_sync(0xFFFFFFFFu, v[s].w < 0.0f);
            if (lane == 0) {
                base[(j0 + 0) * 128] = w0;
                base[(j0 + 1) * 128] = w1;
                base[(j0 + 2) * 128] = w2;
                base[(j0 + 3) * 128] = w3;
            }
        }
    } else {
        // ---- B role: word j = 4*by + q, bit l = sign(kern[128*by + 4l + q][n]) ----
        int bid = blockIdx.x - PACKA_BLOCKS;
        int n0 = (bid & 63) * 32;
        int by = bid >> 6;
        int kb = by * 128;
        int tx = tid & 31, ty = tid >> 5;     // (32, 8)
#pragma unroll
        for (int s = 0; s < 16; s++) {
            int k = ty + s * 8;
            float v = kern[(size_t)(kb + k) * NUNITS + n0 + tx];
            tile[k * 33 + tx] = (v < 0.0f) ? 1 : 0;
        }
        __syncthreads();

        int lane = tx;                        // warp = ty
#pragma unroll
        for (int nl = 0; nl < 4; nl++) {
            int n = n0 + ty * 4 + nl;
            uint32_t* dst = bbits + (size_t)(n >> 6) * (KW * 64) + (n & 63);
#pragma unroll
            for (int q = 0; q < 4; q++) {
                uint8_t val = tile[(4 * lane + q) * 33 + (ty * 4 + nl)];
                uint32_t word = __ballot_sync(0xFFFFFFFFu, val != 0);
                if (lane == 0)
                    dst[(by * 4 + q) * 64] = word;
            }
        }
    }
}

// ============================ popcount GEMM ============================
// 128x64 tile, 512 threads, per-thread 4x4 -> ~55 live regs, 64-reg cap,
// 2 CTAs/SM = 32 warps (50% occ) to cover LDS latency and saturate the alu port.
// out[m][n] = 2048 - 2 * sum_j popc(A[m][j] ^ B[n][j]) + bias[n]

__global__ void __launch_bounds__(512, 2) popc_gemm(
    const uint32_t* __restrict__ Ab, const uint32_t* __restrict__ Bb,
    const float* __restrict__ bias, float* __restrict__ out)
{
    extern __shared__ uint32_t smem[];        // A 8192 words, B 4096 words, k1/k2
    uint32_t* Asm = smem;
    uint32_t* Bsm = smem + KW * 128;
    int* ksm = (int*)(smem + KW * 128 + KW * 64);

    const int tid = threadIdx.x;
    const int nblk = blockIdx.x, mblk = blockIdx.y;

    if (tid == 0) { ksm[0] = 1; ksm[1] = 2; }

    {
        const uint4* gA = (const uint4*)(Ab + (size_t)mblk * (KW * 128));
        uint4* sA = (uint4*)Asm;
#pragma unroll
        for (int i = 0; i < 4; i++)
            sA[tid + i * 512] = gA[tid + i * 512];
        const uint4* gB = (const uint4*)(Bb + (size_t)nblk * (KW * 64));
        uint4* sB = (uint4*)Bsm;
#pragma unroll
        for (int i = 0; i < 2; i++)
            sB[tid + i * 512] = gB[tid + i * 512];
    }
    __syncthreads();

    const int k1 = ksm[0];                    // == 1, opaque -> IMAD on fma pipe
    const int k2 = ksm[1];                    // == 2, opaque
    const int tx = tid & 15;                  // 16 n-subblocks x 4 cols
    const int ty = tid >> 4;                  // 32 m-subblocks x 4 rows

    int acc[4][4];
#pragma unroll
    for (int i = 0; i < 4; i++)
#pragma unroll
        for (int k = 0; k < 4; k++) acc[i][k] = 0;

    // 20 CSA triples (words 0..59)
#pragma unroll 2
    for (int jg = 0; jg < 20; jg++) {
        uint32_t a0[4], a1[4], a2[4], b0[4], b1[4], b2[4];
        const uint32_t* Ap = &Asm[(jg * 3) * 128 + ty * 4];
        const uint32_t* Bp = &Bsm[(jg * 3) * 64 + tx * 4];
        *(uint4*)&a0[0] = *(const uint4*)&Ap[0];
        *(uint4*)&a1[0] = *(const uint4*)&Ap[128];
        *(uint4*)&a2[0] = *(const uint4*)&Ap[256];
        *(uint4*)&b0[0] = *(const uint4*)&Bp[0];
        *(uint4*)&b1[0] = *(const uint4*)&Bp[64];
        *(uint4*)&b2[0] = *(const uint4*)&Bp[128];
#pragma unroll
        for (int mi = 0; mi < 4; mi++) {
#pragma unroll
            for (int ni = 0; ni < 4; ni++) {
                uint32_t x0 = a0[mi] ^ b0[ni];
                uint32_t x1 = a1[mi] ^ b1[ni];
                uint32_t x2 = a2[mi] ^ b2[ni];
                uint32_t s = x0 ^ x1 ^ x2;                      // LOP3 0x96
                uint32_t c = (x0 & x1) | (x2 & (x0 | x1));      // LOP3 0xE8
                int a = acc[mi][ni];
                a = __popc(s) * k1 + a;                         // IMAD (fma pipe)
                a = __popc(c) * k2 + a;                         // IMAD (fma pipe)
                acc[mi][ni] = a;
            }
        }
    }
    // raw tail: words 60..63
    {
        uint32_t a0[4], a1[4], a2[4], a3[4], b0[4], b1[4], b2[4], b3[4];
        const uint32_t* Ap = &Asm[60 * 128 + ty * 4];
        const uint32_t* Bp = &Bsm[60 * 64 + tx * 4];
        *(uint4*)&a0[0] = *(const uint4*)&Ap[0];
        *(uint4*)&a1[0] = *(const uint4*)&Ap[128];
        *(uint4*)&a2[0] = *(const uint4*)&Ap[256];
        *(uint4*)&a3[0] = *(const uint4*)&Ap[384];
        *(uint4*)&b0[0] = *(const uint4*)&Bp[0];
        *(uint4*)&b1[0] = *(const uint4*)&Bp[64];
        *(uint4*)&b2[0] = *(const uint4*)&Bp[128];
        *(uint4*)&b3[0] = *(const uint4*)&Bp[192];
#pragma unroll
        for (int mi = 0; mi < 4; mi++) {
#pragma unroll
            for (int ni = 0; ni < 4; ni++) {
                int a = acc[mi][ni];
                a = __popc(a0[mi] ^ b0[ni]) * k1 + a;
                a = __popc(a1[mi] ^ b1[ni]) * k1 + a;
                a = __popc(a2[mi] ^ b2[ni]) * k1 + a;
                a = __popc(a3[mi] ^ b3[ni]) * k1 + a;
                acc[mi][ni] = a;
            }
        }
    }

    // epilogue: val = 2048 - 2*acc + bias
    const int n0 = nblk * 64 + tx * 4;
    float bl[4];
    *(float4*)&bl[0] = *(const float4*)&bias[n0];
#pragma unroll
    for (int i = 0; i < 4; i++) bl[i] += 2048.0f;

#pragma unroll
    for (int mi = 0; mi < 4; mi++) {
        size_t row = (size_t)(mblk * 128 + ty * 4 + mi) * NUNITS + n0;
        float4 v0;
        v0.x = fmaf(-2.0f, (float)acc[mi][0], bl[0]);
        v0.y = fmaf(-2.0f, (float)acc[mi][1], bl[1]);
        v0.z = fmaf(-2.0f, (float)acc[mi][2], bl[2]);
        v0.w = fmaf(-2.0f, (float)acc[mi][3], bl[3]);
        *(float4*)&out[row] = v0;
    }
}

// ============================ Host ============================

#define GEMM_SMEM ((KW * 128 + KW * 64) * 4 + 16)   // 48 KB + k1/k2 -> 2 CTAs/SM

extern "C" void kernel_launch(void* const* d_in, const int* in_sizes, int n_in,
                              void* d_out, int out_size) {
    const float* inputs = (const float*)d_in[0];
    const float* kern   = (const float*)d_in[1];
    const float* bias   = (const float*)d_in[2];
    float* out = (float*)d_out;

    void *pA = nullptr, *pB = nullptr;
    cudaGetSymbolAddress(&pA, g_Abits);
    cudaGetSymbolAddress(&pB, g_Bbits);

    // 1) merged packs: one launch
    pack_all<<<PACKA_BLOCKS + 1024, 256>>>(inputs, kern, (uint32_t*)pA, (uint32_t*)pB);

    // 2) CSA popcount GEMM: 128x64 tiles, 512 threads, 2 CTAs/SM (32 warps)
    cudaFuncSetAttribute(popc_gemm, cudaFuncAttributeMaxDynamicSharedMemorySize, GEMM_SMEM);
    dim3 grid(NUNITS / 64, BDIM / 128);        // (32, 64) = 2048 CTAs
    popc_gemm<<<grid, 512, GEMM_SMEM>>>((const uint32_t*)pA, (const uint32_t*)pB, bias, out);
}